// round 15
// baseline (speedup 1.0000x reference)
#include <cuda_runtime.h>
#include <cuda_fp16.h>
#include <cstdint>

// Problem constants
#define Bc    32
#define Dc    256
#define HWc   1024
#define Nrows 32768          // B*H*W
#define Kc    2048
#define QN    8388608        // quantized element count (B*D*H*W)
#define IDX_OFF (QN + 2)     // out: [quantized(QN), loss, perplexity, indices(Nrows)]

// Scratch (device globals: no allocation allowed)
__device__ float   g_Et[Kc * Dc];       // transposed codebook (K, D) fp32
__device__ float   g_enorm[Kc];         // ||e_k||^2
__device__ __half  g_Eh[Kc * Dc];       // codebook fp16 (K, D)
__device__ __half  g_Xh[Nrows * Dc];    // clamped inputs fp16 (N, D)
__device__ float   g_Xf[Nrows * Dc];    // clamped inputs fp32 (N, D) for exact fallback
__device__ int     g_idx[Nrows];        // argmin indices
__device__ int     g_counts[Kc];        // usage histogram
__device__ int     g_nfb;               // fallback row count
__device__ int     g_fb[Nrows];         // fallback row list
__device__ unsigned long long g_bkey[Nrows];  // fallback result keys
__device__ float   g_part[1024];        // per-block partial sums of (q-x)^2

// ---------------------------------------------------------------------------
// helpers
// ---------------------------------------------------------------------------
__device__ __forceinline__ uint32_t smem_u32(const void* p) {
    uint32_t a;
    asm("{ .reg .u64 t; cvta.to.shared.u64 t, %1; cvt.u32.u64 %0, t; }"
        : "=r"(a) : "l"(p));
    return a;
}

#define STS128(addr, v) \
    asm volatile("st.shared.v4.b32 [%0], {%1, %2, %3, %4};" \
                 :: "r"(addr), "r"((v).x), "r"((v).y), "r"((v).z), "r"((v).w) : "memory")

#define CPASYNC16(dst, src) \
    asm volatile("cp.async.cg.shared.global [%0], [%1], 16;" \
                 :: "r"(dst), "l"(src) : "memory")
#define CPASYNC_COMMIT() asm volatile("cp.async.commit_group;" ::: "memory")
#define CPASYNC_WAIT0()  asm volatile("cp.async.wait_group 0;" ::: "memory")
#define CPASYNC_WAIT1()  asm volatile("cp.async.wait_group 1;" ::: "memory")

#define LDSM4(r0, r1, r2, r3, addr) \
    asm volatile("ldmatrix.sync.aligned.m8n8.x4.shared.b16 {%0,%1,%2,%3}, [%4];" \
                 : "=r"(r0), "=r"(r1), "=r"(r2), "=r"(r3) : "r"(addr))

#define MMA16816(d, a, b0, b1) \
    asm volatile("mma.sync.aligned.m16n8k16.row.col.f32.f16.f16.f32 " \
                 "{%0,%1,%2,%3}, {%4,%5,%6,%7}, {%8,%9}, {%0,%1,%2,%3};" \
                 : "+f"((d)[0]), "+f"((d)[1]), "+f"((d)[2]), "+f"((d)[3]) \
                 : "r"((a)[0]), "r"((a)[1]), "r"((a)[2]), "r"((a)[3]), \
                   "r"(b0), "r"(b1))

// ---------------------------------------------------------------------------
// K1 (launch 1): embedding (D,K) -> Et (K,D) fp32 + Eh fp16 + deterministic
//   norms. Per-call accumulator zeroing fused here (16384 threads total).
// ---------------------------------------------------------------------------
__global__ void __launch_bounds__(256) k_prep_e(const float* __restrict__ emb) {
    {
        int tg = blockIdx.x * 256 + threadIdx.x;   // 16384 threads
        if (tg < Kc) g_counts[tg] = 0;
        g_bkey[tg] = ~0ull;
        g_bkey[tg + 16384] = ~0ull;
        if (tg == 0) g_nfb = 0;
    }
    __shared__ float tile[256][33];   // [d][kk], padded
    const int k0 = blockIdx.x * 32;
    const int tid = threadIdx.x;
#pragma unroll
    for (int i = 0; i < 32; i++) {
        int u = tid + i * 256;
        int d = u >> 5, kk = u & 31;
        tile[d][kk] = emb[d * Kc + k0 + kk];
    }
    __syncthreads();
#pragma unroll
    for (int i = 0; i < 32; i++) {
        int u = tid + i * 256;
        int kk = u >> 8, d = u & 255;
        float v = tile[d][kk];
        int idx = (k0 + kk) * Dc + d;
        g_Et[idx] = v;
        g_Eh[idx] = __float2half(v);
    }
    const int kk = tid >> 3, h = tid & 7;
    float s = 0.f;
#pragma unroll
    for (int j = 0; j < 32; j++) {
        float v = tile[h + 8 * j][kk];
        s += v * v;
    }
    s += __shfl_down_sync(0xffffffffu, s, 4);
    s += __shfl_down_sync(0xffffffffu, s, 2);
    s += __shfl_down_sync(0xffffffffu, s, 1);
    if (h == 0) g_enorm[k0 + kk] = s;
}

// ---------------------------------------------------------------------------
// K2 (launch 2): inputs (B,D,H,W) -> clamped (N,D) fp32 + fp16
// ---------------------------------------------------------------------------
__global__ void k_prep_x(const float* __restrict__ in) {
    __shared__ float tile[32][33];
    int p0 = blockIdx.x * 32, d0 = blockIdx.y * 32, b = blockIdx.z;
    int tx = threadIdx.x, ty = threadIdx.y;   // block (32, 8)
    const float* ib = in + (size_t)b * (Dc * HWc);
#pragma unroll
    for (int i = 0; i < 32; i += 8)
        tile[ty + i][tx] = ib[(d0 + ty + i) * HWc + p0 + tx];
    __syncthreads();
#pragma unroll
    for (int i = 0; i < 32; i += 8) {
        float v = tile[tx][ty + i];
        v = fminf(fmaxf(v, -10.f), 10.f);
        int row = b * HWc + p0 + ty + i;
        g_Xf[(size_t)row * Dc + d0 + tx] = v;
        g_Xh[(size_t)row * Dc + d0 + tx] = __float2half(v);
    }
}

// ---------------------------------------------------------------------------
// K3 (launch 3): mma.sync fp16 distance GEMM + fused argmin.
//   CTA: 128 rows x all 2048 codewords, 256 threads (8 warps = 2M x 4N,
//   warp tile 64x32). A tile [128x256] fp16 swizzled (64KB); B streamed as
//   64 chunks (16KB) via a 3-STAGE cp.async pipeline (wait_group 1): each
//   load has two chunk-periods to land. Norms prefetched into registers at
//   chunk c==0 (8 per thread), used at c==3. smem 112KB -> 2 CTAs/SM.
// ---------------------------------------------------------------------------
#define OFF_B   65536                   // A: [0, 64KB); B: 3 x 16KB
#define SMEM_TOTAL 114688               // 112KB
#define NCHUNKS 64                      // 16 N-tiles * 4 k-chunks
#define MARGIN_TH 0.08f

__device__ __forceinline__ void issue_chunk(int g, uint32_t smB, int tid) {
    if (g < NCHUNKS) {
        const int nt = g >> 2, c = g & 3;
        const uint4* Bg = (const uint4*)g_Eh;   // 32 16B-units per codeword row
        const uint32_t buf = smB + (uint32_t)(g % 3) * 16384u;
#pragma unroll
        for (int i = 0; i < 4; i++) {
            int u = tid + i * 256;
            int row = u >> 3, c16 = u & 7;
            const uint4* src = Bg + (((nt * 128 + row) << 5) + c * 8 + c16);
            uint32_t dst = buf + (uint32_t)(row * 128 + ((c16 ^ (row & 7)) << 4));
            CPASYNC16(dst, src);
        }
    }
    CPASYNC_COMMIT();
}

__global__ void __launch_bounds__(256, 2) k_argmin_mma() {
    extern __shared__ __align__(1024) char sm[];
    const uint32_t smb = smem_u32(sm);
    const uint32_t smA = smb;
    const uint32_t smB = smb + OFF_B;
    float* rv  = (float*)sm;                    // aliased onto A after drain
    float* rv2 = rv + 2048;
    int*   ri  = (int*)(rv2 + 2048);

    const int tid  = threadIdx.x;
    const int lane = tid & 31;
    const int wid  = tid >> 5;
    const int wm = wid & 1;          // M group (0..1), 64 rows each
    const int wn = wid >> 1;         // N group (0..3), 32 cols each
    const int gid = lane >> 2;
    const int tid4 = lane & 3;
    const int m0 = blockIdx.x * 128;

    // ---- load A tile [128 x 256] fp16, swizzled: 4096 uint4 / 256 thr = 16 it
    {
        const uint4* Xg = (const uint4*)g_Xh;
#pragma unroll
        for (int i = 0; i < 16; i++) {
            int u = tid + i * 256;
            int row = u >> 5, c16 = u & 31;
            uint4 v = Xg[(size_t)(m0 + row) * 32 + c16];
            uint32_t dst = smA + (uint32_t)(row * 512 + ((c16 ^ (row & 7)) << 4));
            STS128(dst, v);
        }
    }
    issue_chunk(0, smB, tid);
    issue_chunk(1, smB, tid);
    __syncthreads();

    float acc[4][4][4];
#pragma unroll
    for (int i = 0; i < 4; i++)
#pragma unroll
        for (int j = 0; j < 4; j++)
#pragma unroll
            for (int c = 0; c < 4; c++) acc[i][j][c] = 0.f;

    float best[8], best2[8];
    int bidx[8];
#pragma unroll
    for (int s = 0; s < 8; s++) { best[s] = 3.4e38f; best2[s] = 3.4e38f; bidx[s] = 0; }

    float enr[8];

    for (int g = 0; g < NCHUNKS; g++) {
        CPASYNC_WAIT1();                 // chunk g landed (g+1 may be in flight)
        __syncthreads();                 // compute g-1 done by all warps
        issue_chunk(g + 2, smB, tid);    // buf (g+2)%3, last used by chunk g-1

        const int nt = g >> 2, c = g & 3;
        const uint32_t bufB = smB + (uint32_t)(g % 3) * 16384u;

        if (c == 0) {
            // prefetch this N-tile's norms (used at c==3; L2 latency hidden)
            const float* en = g_enorm + nt * 128 + wn * 32 + tid4 * 2;
#pragma unroll
            for (int j = 0; j < 4; j++) {
                enr[j * 2]     = en[j * 8];
                enr[j * 2 + 1] = en[j * 8 + 1];
            }
        }

#pragma unroll
        for (int s = 0; s < 4; s++) {
            uint32_t a[4][4];
#pragma unroll
            for (int i = 0; i < 4; i++) {
                int row = wm * 64 + i * 16 + (lane & 15);
                int c16 = c * 8 + s * 2 + (lane >> 4);
                uint32_t addr = smA + (uint32_t)(row * 512 + ((c16 ^ (row & 7)) << 4));
                LDSM4(a[i][0], a[i][1], a[i][2], a[i][3], addr);
            }
#pragma unroll
            for (int j16 = 0; j16 < 2; j16++) {
                uint32_t b0, b1, b2, b3;
                int row = wn * 32 + j16 * 16 + (lane & 7) + ((lane & 16) ? 8 : 0);
                int c16 = s * 2 + ((lane >> 3) & 1);
                uint32_t addr = bufB + (uint32_t)(row * 128 + ((c16 ^ (row & 7)) << 4));
                LDSM4(b0, b1, b2, b3, addr);
#pragma unroll
                for (int i = 0; i < 4; i++) {
                    MMA16816(acc[i][j16 * 2],     a[i], b0, b1);
                    MMA16816(acc[i][j16 * 2 + 1], a[i], b2, b3);
                }
            }
        }

        if (c == 3) {
            // epilogue: distances + running argmin for this 128-codeword tile
#pragma unroll
            for (int i = 0; i < 4; i++)
#pragma unroll
                for (int j = 0; j < 4; j++)
#pragma unroll
                    for (int cc = 0; cc < 4; cc++) {
                        int n = nt * 128 + wn * 32 + j * 8 + tid4 * 2 + (cc & 1);
                        float d = enr[j * 2 + (cc & 1)] - 2.f * acc[i][j][cc];
                        int sl = i * 2 + (cc >> 1);
                        if (d < best[sl]) {
                            best2[sl] = best[sl]; best[sl] = d; bidx[sl] = n;
                        } else if (d < best2[sl]) {
                            best2[sl] = d;
                        }
                        acc[i][j][cc] = 0.f;
                    }
        }
    }

    // drain async copies, then alias reduction arrays onto A smem
    CPASYNC_WAIT0();
    __syncthreads();

    // ---- cross-warp argmin reduction (16 candidates per row, 128 rows) ----
#pragma unroll
    for (int sl = 0; sl < 8; sl++) {
        int i = sl >> 1, h = sl & 1;
        int row = wm * 64 + i * 16 + gid + 8 * h;
        int s16 = wn * 4 + tid4;
        rv[row * 16 + s16]  = best[sl];
        rv2[row * 16 + s16] = best2[sl];
        ri[row * 16 + s16]  = bidx[sl];
    }
    __syncthreads();

    if (tid < 128) {
        float b1 = rv[tid * 16], b2 = rv2[tid * 16];
        int bi = ri[tid * 16];
#pragma unroll
        for (int s = 1; s < 16; s++) {
            float v = rv[tid * 16 + s], v2 = rv2[tid * 16 + s];
            int idx = ri[tid * 16 + s];
            if (v < b1 || (v == b1 && idx < bi)) {
                b2 = fminf(b1, v2);
                b1 = v; bi = idx;
            } else {
                b2 = fminf(b2, v);
            }
        }
        g_idx[m0 + tid] = bi;
        if (b2 - b1 < MARGIN_TH) {
            int p = atomicAdd(&g_nfb, 1);
            g_fb[p] = m0 + tid;
        }
    }
}

// ---------------------------------------------------------------------------
// K4 (launch 4, PROFILED): exact fp32 re-solve for flagged rows.
//   Grid (8 codeword-slices, 64 row-groups). Each CTA: 32 rows in smem,
//   one thread per codeword; codeword chunk in REGISTERS across the row
//   loop. Warp-reduced atomicMin on order-preserving (dist_bits<<32|idx).
// ---------------------------------------------------------------------------
__global__ void __launch_bounds__(256) k_fallback() {
    __shared__ float xr[32][256];
    __shared__ int rows[32];
    const int n = g_nfb;
    const int k0 = blockIdx.x * 256;
    const int t = threadIdx.x;
    for (int grp = blockIdx.y; grp * 32 < n; grp += gridDim.y) {
        const int cnt = min(32, n - grp * 32);
        __syncthreads();
        if (t < cnt) rows[t] = g_fb[grp * 32 + t];
        __syncthreads();
#pragma unroll
        for (int i = 0; i < 32; i++) {
            int u = t + i * 256;
            int r = u >> 8, d = u & 255;
            if (r < cnt) xr[r][d] = g_Xf[(size_t)rows[r] * Dc + d];
        }
        __syncthreads();
        const int k = k0 + t;
        const float en = g_enorm[k];
        const float4* e4 = (const float4*)(g_Et + (size_t)k * Dc);
        float acc[32];
#pragma unroll
        for (int r = 0; r < 32; r++) acc[r] = 0.f;
#pragma unroll
        for (int ch = 0; ch < 8; ch++) {
            float4 e[8];
#pragma unroll
            for (int j = 0; j < 8; j++) e[j] = e4[ch * 8 + j];
            for (int r = 0; r < cnt; r++) {
                const float4* x4 = (const float4*)&xr[r][ch * 32];
                float s = 0.f;
#pragma unroll
                for (int j = 0; j < 8; j++) {
                    float4 x = x4[j];
                    s += e[j].x * x.x;
                    s += e[j].y * x.y;
                    s += e[j].z * x.z;
                    s += e[j].w * x.w;
                }
                acc[r] += s;
            }
        }
        for (int r = 0; r < cnt; r++) {
            float dist = en - 2.f * acc[r];
            uint32_t b = __float_as_uint(dist);
            b = (b & 0x80000000u) ? ~b : (b | 0x80000000u);
            unsigned long long key = ((unsigned long long)b << 32) | (unsigned)k;
#pragma unroll
            for (int o = 16; o; o >>= 1) {
                unsigned long long other = __shfl_xor_sync(0xffffffffu, key, o);
                key = min(key, other);
            }
            if ((t & 31) == 0) atomicMin(&g_bkey[rows[r]], key);
        }
    }
}

// ---------------------------------------------------------------------------
// K5 (launch 5): gather + hist fused. Block = 32 rows (one p-slice of one
//   image) x all 256 d. Codebook rows staged COALESCED into padded smem;
//   in/out accesses 128B-coalesced. bkey fixup + index + histogram here.
// ---------------------------------------------------------------------------
__global__ void __launch_bounds__(256) k_gather(const float* __restrict__ in,
                                                float* __restrict__ out) {
    __shared__ float qs[32][257];   // [p][d], padded
    __shared__ int ks[32];
    __shared__ float ws[8];
    const int t = threadIdx.x;
    const int p0 = blockIdx.x * 32;
    const int b  = blockIdx.y;
    const int base = b * HWc + p0;
    if (t < 32) {
        int row = base + t;
        unsigned long long key = g_bkey[row];
        int k = (key != ~0ull) ? (int)(key & 0xFFFFFFFFu) : g_idx[row];
        ks[t] = k;
        out[IDX_OFF + row] = (float)k;
        atomicAdd(&g_counts[k], 1);
    }
    __syncthreads();
#pragma unroll
    for (int i = 0; i < 8; i++) {
        int u = t + i * 256;
        int r = u >> 6, j = u & 63;
        float4 v = ((const float4*)(g_Et + (size_t)ks[r] * Dc))[j];
        qs[r][j * 4 + 0] = v.x;
        qs[r][j * 4 + 1] = v.y;
        qs[r][j * 4 + 2] = v.z;
        qs[r][j * 4 + 3] = v.w;
    }
    __syncthreads();
    const int p = t & 31, dg = t >> 5;
    float s = 0.f;
#pragma unroll
    for (int dd = 0; dd < 32; dd++) {
        int d = dg * 32 + dd;
        float q = qs[p][d];
        size_t o = ((size_t)(b * Dc + d) << 10) + p0 + p;
        float x = in[o];
        out[o] = q;
        float df = q - x;
        s += df * df;
    }
#pragma unroll
    for (int o = 16; o; o >>= 1) s += __shfl_xor_sync(0xffffffffu, s, o);
    int lane = t & 31, w = t >> 5;
    if (lane == 0) ws[w] = s;
    __syncthreads();
    if (t == 0) {
        g_part[b * 32 + blockIdx.x] = ws[0] + ws[1] + ws[2] + ws[3]
                                    + ws[4] + ws[5] + ws[6] + ws[7];
    }
}

// ---------------------------------------------------------------------------
// K6 (launch 6): finalize loss + perplexity (deterministic fp64 reductions)
// ---------------------------------------------------------------------------
__global__ void k_final(float* __restrict__ out) {
    __shared__ double sh[256];
    __shared__ double sq[256];
    int t = threadIdx.x;
    double local = 0.0;
    for (int k = t; k < Kc; k += 256) {
        double pr = (double)g_counts[k] / (double)Nrows;
        local += pr * log(pr + 1e-10);
    }
    double lsum = 0.0;
    for (int i = t; i < 1024; i += 256) lsum += (double)g_part[i];
    sh[t] = local;
    sq[t] = lsum;
    __syncthreads();
    for (int o = 128; o; o >>= 1) {
        if (t < o) { sh[t] += sh[t + o]; sq[t] += sq[t + o]; }
        __syncthreads();
    }
    if (t == 0) {
        out[QN]     = (float)(1.25 * sq[0] / (double)QN);
        out[QN + 1] = (float)exp(-sh[0]);
    }
}

// ---------------------------------------------------------------------------
extern "C" void kernel_launch(void* const* d_in, const int* in_sizes, int n_in,
                              void* d_out, int out_size) {
    const float* in  = (const float*)d_in[0];
    const float* emb = (const float*)d_in[1];
    if (n_in >= 2 && in_sizes[0] == Dc * Kc) {  // defensive: inputs swapped?
        in  = (const float*)d_in[1];
        emb = (const float*)d_in[0];
    }
    float* out = (float*)d_out;

    cudaFuncSetAttribute(k_argmin_mma, cudaFuncAttributeMaxDynamicSharedMemorySize,
                         SMEM_TOTAL);

    k_prep_e<<<Kc / 32, 256>>>(emb);                       // #1 (zero fused)
    k_prep_x<<<dim3(HWc / 32, Dc / 32, Bc), dim3(32, 8)>>>(in);   // #2
    k_argmin_mma<<<Nrows / 128, 256, SMEM_TOTAL>>>();      // #3
    k_fallback<<<dim3(8, 64), 256>>>();                    // #4 -> profiled
    k_gather<<<dim3(HWc / 32, Bc), 256>>>(in, out);        // #5 (hist fused)
    k_final<<<1, 256>>>(out);                              // #6
}

// round 17
// speedup vs baseline: 1.1210x; 1.1210x over previous
#include <cuda_runtime.h>
#include <cuda_fp16.h>
#include <cstdint>

// Problem constants
#define Bc    32
#define Dc    256
#define HWc   1024
#define Nrows 32768          // B*H*W
#define Kc    2048
#define QN    8388608        // quantized element count (B*D*H*W)
#define IDX_OFF (QN + 2)     // out: [quantized(QN), loss, perplexity, indices(Nrows)]

// Scratch (device globals: no allocation allowed)
__device__ float   g_Et[Kc * Dc];       // transposed codebook (K, D) fp32
__device__ float   g_enorm[Kc];         // ||e_k||^2
__device__ __half  g_Eh[Kc * Dc];       // codebook fp16 (K, D)
__device__ __half  g_Xh[Nrows * Dc];    // clamped inputs fp16 (N, D)
__device__ float   g_Xf[Nrows * Dc];    // clamped inputs fp32 (N, D) for exact fallback
__device__ int     g_idx[Nrows];        // argmin indices
__device__ int     g_counts[Kc];        // usage histogram
__device__ int     g_nfb;               // fallback row count
__device__ int     g_fb[Nrows];         // fallback row list
__device__ unsigned long long g_bkey[Nrows];  // fallback result keys
__device__ float   g_part[1024];        // per-block partial sums of (q-x)^2

// ---------------------------------------------------------------------------
// helpers
// ---------------------------------------------------------------------------
__device__ __forceinline__ uint32_t smem_u32(const void* p) {
    uint32_t a;
    asm("{ .reg .u64 t; cvta.to.shared.u64 t, %1; cvt.u32.u64 %0, t; }"
        : "=r"(a) : "l"(p));
    return a;
}

#define STS128(addr, v) \
    asm volatile("st.shared.v4.b32 [%0], {%1, %2, %3, %4};" \
                 :: "r"(addr), "r"((v).x), "r"((v).y), "r"((v).z), "r"((v).w) : "memory")

#define CPASYNC16(dst, src) \
    asm volatile("cp.async.cg.shared.global [%0], [%1], 16;" \
                 :: "r"(dst), "l"(src) : "memory")
#define CPASYNC_COMMIT() asm volatile("cp.async.commit_group;" ::: "memory")
#define CPASYNC_WAIT0()  asm volatile("cp.async.wait_group 0;" ::: "memory")

#define LDSM4(r0, r1, r2, r3, addr) \
    asm volatile("ldmatrix.sync.aligned.m8n8.x4.shared.b16 {%0,%1,%2,%3}, [%4];" \
                 : "=r"(r0), "=r"(r1), "=r"(r2), "=r"(r3) : "r"(addr))

#define MMA16816(d, a, b0, b1) \
    asm volatile("mma.sync.aligned.m16n8k16.row.col.f32.f16.f16.f32 " \
                 "{%0,%1,%2,%3}, {%4,%5,%6,%7}, {%8,%9}, {%0,%1,%2,%3};" \
                 : "+f"((d)[0]), "+f"((d)[1]), "+f"((d)[2]), "+f"((d)[3]) \
                 : "r"((a)[0]), "r"((a)[1]), "r"((a)[2]), "r"((a)[3]), \
                   "r"(b0), "r"(b1))

// ---------------------------------------------------------------------------
// K1 (launch 1): embedding (D,K) -> Et (K,D) fp32 + Eh fp16 + deterministic
//   norms. Per-call accumulator zeroing fused here (16384 threads total).
// ---------------------------------------------------------------------------
__global__ void __launch_bounds__(256) k_prep_e(const float* __restrict__ emb) {
    {
        int tg = blockIdx.x * 256 + threadIdx.x;   // 16384 threads
        if (tg < Kc) g_counts[tg] = 0;
        g_bkey[tg] = ~0ull;
        g_bkey[tg + 16384] = ~0ull;
        if (tg == 0) g_nfb = 0;
    }
    __shared__ float tile[256][33];   // [d][kk], padded
    const int k0 = blockIdx.x * 32;
    const int tid = threadIdx.x;
#pragma unroll
    for (int i = 0; i < 32; i++) {
        int u = tid + i * 256;
        int d = u >> 5, kk = u & 31;
        tile[d][kk] = emb[d * Kc + k0 + kk];
    }
    __syncthreads();
#pragma unroll
    for (int i = 0; i < 32; i++) {
        int u = tid + i * 256;
        int kk = u >> 8, d = u & 255;
        float v = tile[d][kk];
        int idx = (k0 + kk) * Dc + d;
        g_Et[idx] = v;
        g_Eh[idx] = __float2half(v);
    }
    const int kk = tid >> 3, h = tid & 7;
    float s = 0.f;
#pragma unroll
    for (int j = 0; j < 32; j++) {
        float v = tile[h + 8 * j][kk];
        s += v * v;
    }
    s += __shfl_down_sync(0xffffffffu, s, 4);
    s += __shfl_down_sync(0xffffffffu, s, 2);
    s += __shfl_down_sync(0xffffffffu, s, 1);
    if (h == 0) g_enorm[k0 + kk] = s;
}

// ---------------------------------------------------------------------------
// K2 (launch 2): inputs (B,D,H,W) -> clamped (N,D) fp32 + fp16
// ---------------------------------------------------------------------------
__global__ void k_prep_x(const float* __restrict__ in) {
    __shared__ float tile[32][33];
    int p0 = blockIdx.x * 32, d0 = blockIdx.y * 32, b = blockIdx.z;
    int tx = threadIdx.x, ty = threadIdx.y;   // block (32, 8)
    const float* ib = in + (size_t)b * (Dc * HWc);
#pragma unroll
    for (int i = 0; i < 32; i += 8)
        tile[ty + i][tx] = ib[(d0 + ty + i) * HWc + p0 + tx];
    __syncthreads();
#pragma unroll
    for (int i = 0; i < 32; i += 8) {
        float v = tile[tx][ty + i];
        v = fminf(fmaxf(v, -10.f), 10.f);
        int row = b * HWc + p0 + ty + i;
        g_Xf[(size_t)row * Dc + d0 + tx] = v;
        g_Xh[(size_t)row * Dc + d0 + tx] = __float2half(v);
    }
}

// ---------------------------------------------------------------------------
// K3 (launch 3): mma.sync fp16 distance GEMM + fused argmin.
//   EXACT R14 configuration (measured 129.7us): 128 rows x 2048 codewords,
//   256 threads (8 warps = 2M x 4N, warp tile 64x32), 2-stage cp.async
//   double buffer, norms in smem, 104KB -> 2 CTAs/SM.
// ---------------------------------------------------------------------------
#define OFF_B   65536                   // A: [0, 64KB)
#define OFF_EN  98304                   // B: 2 x 16KB at [64KB, 96KB)
#define SMEM_TOTAL 106496               // en: 8KB at [96KB, 104KB)
#define NCHUNKS 64                      // 16 N-tiles * 4 k-chunks
#define MARGIN_TH 0.08f

__device__ __forceinline__ void issue_chunk(int g, uint32_t smB, int tid) {
    if (g < NCHUNKS) {
        const int nt = g >> 2, c = g & 3;
        const uint4* Bg = (const uint4*)g_Eh;   // 32 16B-units per codeword row
        const uint32_t buf = smB + (uint32_t)(g & 1) * 16384u;
#pragma unroll
        for (int i = 0; i < 4; i++) {
            int u = tid + i * 256;
            int row = u >> 3, c16 = u & 7;
            const uint4* src = Bg + (((nt * 128 + row) << 5) + c * 8 + c16);
            uint32_t dst = buf + (uint32_t)(row * 128 + ((c16 ^ (row & 7)) << 4));
            CPASYNC16(dst, src);
        }
    }
    CPASYNC_COMMIT();
}

__global__ void __launch_bounds__(256, 2) k_argmin_mma() {
    extern __shared__ __align__(1024) char sm[];
    const uint32_t smb = smem_u32(sm);
    const uint32_t smA = smb;
    const uint32_t smB = smb + OFF_B;
    float* s_en = (float*)(sm + OFF_EN);
    float* rv  = (float*)sm;                    // aliased onto A after drain
    float* rv2 = rv + 2048;
    int*   ri  = (int*)(rv2 + 2048);

    const int tid  = threadIdx.x;
    const int lane = tid & 31;
    const int wid  = tid >> 5;
    const int wm = wid & 1;          // M group (0..1), 64 rows each
    const int wn = wid >> 1;         // N group (0..3), 32 cols each
    const int gid = lane >> 2;
    const int tid4 = lane & 3;
    const int m0 = blockIdx.x * 128;

    // ---- load A tile [128 x 256] fp16, swizzled: 4096 uint4 / 256 thr = 16 it
    {
        const uint4* Xg = (const uint4*)g_Xh;
#pragma unroll
        for (int i = 0; i < 16; i++) {
            int u = tid + i * 256;
            int row = u >> 5, c16 = u & 31;
            uint4 v = Xg[(size_t)(m0 + row) * 32 + c16];
            uint32_t dst = smA + (uint32_t)(row * 512 + ((c16 ^ (row & 7)) << 4));
            STS128(dst, v);
        }
#pragma unroll
        for (int i = 0; i < 8; i++) s_en[tid + i * 256] = g_enorm[tid + i * 256];
    }
    issue_chunk(0, smB, tid);
    __syncthreads();

    float acc[4][4][4];
#pragma unroll
    for (int i = 0; i < 4; i++)
#pragma unroll
        for (int j = 0; j < 4; j++)
#pragma unroll
            for (int c = 0; c < 4; c++) acc[i][j][c] = 0.f;

    float best[8], best2[8];
    int bidx[8];
#pragma unroll
    for (int s = 0; s < 8; s++) { best[s] = 3.4e38f; best2[s] = 3.4e38f; bidx[s] = 0; }

    for (int g = 0; g < NCHUNKS; g++) {
        CPASYNC_WAIT0();                 // chunk g landed (only pending group)
        __syncthreads();                 // all warps done with buf (g+1)&1 too
        issue_chunk(g + 1, smB, tid);    // overlaps with compute of chunk g

        const int nt = g >> 2, c = g & 3;
        const uint32_t bufB = smB + (uint32_t)(g & 1) * 16384u;

#pragma unroll
        for (int s = 0; s < 4; s++) {
            uint32_t a[4][4];
#pragma unroll
            for (int i = 0; i < 4; i++) {
                int row = wm * 64 + i * 16 + (lane & 15);
                int c16 = c * 8 + s * 2 + (lane >> 4);
                uint32_t addr = smA + (uint32_t)(row * 512 + ((c16 ^ (row & 7)) << 4));
                LDSM4(a[i][0], a[i][1], a[i][2], a[i][3], addr);
            }
#pragma unroll
            for (int j16 = 0; j16 < 2; j16++) {
                uint32_t b0, b1, b2, b3;
                int row = wn * 32 + j16 * 16 + (lane & 7) + ((lane & 16) ? 8 : 0);
                int c16 = s * 2 + ((lane >> 3) & 1);
                uint32_t addr = bufB + (uint32_t)(row * 128 + ((c16 ^ (row & 7)) << 4));
                LDSM4(b0, b1, b2, b3, addr);
#pragma unroll
                for (int i = 0; i < 4; i++) {
                    MMA16816(acc[i][j16 * 2],     a[i], b0, b1);
                    MMA16816(acc[i][j16 * 2 + 1], a[i], b2, b3);
                }
            }
        }

        if (c == 3) {
            // epilogue: distances + running argmin for this 128-codeword tile
#pragma unroll
            for (int i = 0; i < 4; i++)
#pragma unroll
                for (int j = 0; j < 4; j++)
#pragma unroll
                    for (int cc = 0; cc < 4; cc++) {
                        int n = nt * 128 + wn * 32 + j * 8 + tid4 * 2 + (cc & 1);
                        float d = s_en[n] - 2.f * acc[i][j][cc];
                        int sl = i * 2 + (cc >> 1);
                        if (d < best[sl]) {
                            best2[sl] = best[sl]; best[sl] = d; bidx[sl] = n;
                        } else if (d < best2[sl]) {
                            best2[sl] = d;
                        }
                        acc[i][j][cc] = 0.f;
                    }
        }
    }

    // drain async copies, then alias reduction arrays onto A smem
    CPASYNC_WAIT0();
    __syncthreads();

    // ---- cross-warp argmin reduction (16 candidates per row, 128 rows) ----
#pragma unroll
    for (int sl = 0; sl < 8; sl++) {
        int i = sl >> 1, h = sl & 1;
        int row = wm * 64 + i * 16 + gid + 8 * h;
        int s16 = wn * 4 + tid4;
        rv[row * 16 + s16]  = best[sl];
        rv2[row * 16 + s16] = best2[sl];
        ri[row * 16 + s16]  = bidx[sl];
    }
    __syncthreads();

    if (tid < 128) {
        float b1 = rv[tid * 16], b2 = rv2[tid * 16];
        int bi = ri[tid * 16];
#pragma unroll
        for (int s = 1; s < 16; s++) {
            float v = rv[tid * 16 + s], v2 = rv2[tid * 16 + s];
            int idx = ri[tid * 16 + s];
            if (v < b1 || (v == b1 && idx < bi)) {
                b2 = fminf(b1, v2);
                b1 = v; bi = idx;
            } else {
                b2 = fminf(b2, v);
            }
        }
        g_idx[m0 + tid] = bi;
        if (b2 - b1 < MARGIN_TH) {
            int p = atomicAdd(&g_nfb, 1);
            g_fb[p] = m0 + tid;
        }
    }
}

// ---------------------------------------------------------------------------
// K4 (launch 4, PROFILED): exact fp32 re-solve for flagged rows.
//   Grid (8 codeword-slices, 256 row-groups of 16). Thread = codeword.
//   Codeword streamed in DOUBLE-BUFFERED register chunks (next 128B loads
//   while current chunk's 16-row FMA loop runs -> L2 latency overlapped).
//   Warp-reduced atomicMin on order-preserving (dist_bits<<32|idx) key.
// ---------------------------------------------------------------------------
__global__ void __launch_bounds__(256) k_fallback() {
    __shared__ float xr[16][256];
    __shared__ int rows[16];
    const int n = g_nfb;
    const int k0 = blockIdx.x * 256;
    const int t = threadIdx.x;
    for (int grp = blockIdx.y; grp * 16 < n; grp += gridDim.y) {
        const int cnt = min(16, n - grp * 16);
        __syncthreads();
        if (t < cnt) rows[t] = g_fb[grp * 16 + t];
        __syncthreads();
#pragma unroll
        for (int i = 0; i < 16; i++) {
            int u = t + i * 256;
            int r = u >> 8, d = u & 255;
            if (r < cnt) xr[r][d] = g_Xf[(size_t)rows[r] * Dc + d];
        }
        __syncthreads();
        const int k = k0 + t;
        const float en = g_enorm[k];
        const float4* e4 = (const float4*)(g_Et + (size_t)k * Dc);
        float acc[16];
#pragma unroll
        for (int r = 0; r < 16; r++) acc[r] = 0.f;

        float4 ea[8], eb[8];
#pragma unroll
        for (int j = 0; j < 8; j++) ea[j] = e4[j];       // chunk 0
#pragma unroll
        for (int ch = 0; ch < 8; ch++) {
            float4* cur = (ch & 1) ? eb : ea;
            float4* nxt = (ch & 1) ? ea : eb;
            if (ch < 7) {
#pragma unroll
                for (int j = 0; j < 8; j++) nxt[j] = e4[(ch + 1) * 8 + j];
            }
            for (int r = 0; r < cnt; r++) {
                const float4* x4 = (const float4*)&xr[r][ch * 32];
                float s = 0.f;
#pragma unroll
                for (int j = 0; j < 8; j++) {
                    float4 x = x4[j];
                    s += cur[j].x * x.x;
                    s += cur[j].y * x.y;
                    s += cur[j].z * x.z;
                    s += cur[j].w * x.w;
                }
                acc[r] += s;
            }
        }
        for (int r = 0; r < cnt; r++) {
            float dist = en - 2.f * acc[r];
            uint32_t b = __float_as_uint(dist);
            b = (b & 0x80000000u) ? ~b : (b | 0x80000000u);
            unsigned long long key = ((unsigned long long)b << 32) | (unsigned)k;
#pragma unroll
            for (int o = 16; o; o >>= 1) {
                unsigned long long other = __shfl_xor_sync(0xffffffffu, key, o);
                key = min(key, other);
            }
            if ((t & 31) == 0) atomicMin(&g_bkey[rows[r]], key);
        }
    }
}

// ---------------------------------------------------------------------------
// K5 (launch 5): gather + hist fused. Block = 32 rows (one p-slice of one
//   image) x all 256 d. Codebook rows staged COALESCED into padded smem;
//   in/out accesses 128B-coalesced. bkey fixup + index + histogram here.
// ---------------------------------------------------------------------------
__global__ void __launch_bounds__(256) k_gather(const float* __restrict__ in,
                                                float* __restrict__ out) {
    __shared__ float qs[32][257];   // [p][d], padded
    __shared__ int ks[32];
    __shared__ float ws[8];
    const int t = threadIdx.x;
    const int p0 = blockIdx.x * 32;
    const int b  = blockIdx.y;
    const int base = b * HWc + p0;
    if (t < 32) {
        int row = base + t;
        unsigned long long key = g_bkey[row];
        int k = (key != ~0ull) ? (int)(key & 0xFFFFFFFFu) : g_idx[row];
        ks[t] = k;
        out[IDX_OFF + row] = (float)k;
        atomicAdd(&g_counts[k], 1);
    }
    __syncthreads();
#pragma unroll
    for (int i = 0; i < 8; i++) {
        int u = t + i * 256;
        int r = u >> 6, j = u & 63;
        float4 v = ((const float4*)(g_Et + (size_t)ks[r] * Dc))[j];
        qs[r][j * 4 + 0] = v.x;
        qs[r][j * 4 + 1] = v.y;
        qs[r][j * 4 + 2] = v.z;
        qs[r][j * 4 + 3] = v.w;
    }
    __syncthreads();
    const int p = t & 31, dg = t >> 5;
    float s = 0.f;
#pragma unroll
    for (int dd = 0; dd < 32; dd++) {
        int d = dg * 32 + dd;
        float q = qs[p][d];
        size_t o = ((size_t)(b * Dc + d) << 10) + p0 + p;
        float x = in[o];
        out[o] = q;
        float df = q - x;
        s += df * df;
    }
#pragma unroll
    for (int o = 16; o; o >>= 1) s += __shfl_xor_sync(0xffffffffu, s, o);
    int lane = t & 31, w = t >> 5;
    if (lane == 0) ws[w] = s;
    __syncthreads();
    if (t == 0) {
        g_part[b * 32 + blockIdx.x] = ws[0] + ws[1] + ws[2] + ws[3]
                                    + ws[4] + ws[5] + ws[6] + ws[7];
    }
}

// ---------------------------------------------------------------------------
// K6 (launch 6): finalize loss + perplexity (deterministic fp64 reductions)
// ---------------------------------------------------------------------------
__global__ void k_final(float* __restrict__ out) {
    __shared__ double sh[256];
    __shared__ double sq[256];
    int t = threadIdx.x;
    double local = 0.0;
    for (int k = t; k < Kc; k += 256) {
        double pr = (double)g_counts[k] / (double)Nrows;
        local += pr * log(pr + 1e-10);
    }
    double lsum = 0.0;
    for (int i = t; i < 1024; i += 256) lsum += (double)g_part[i];
    sh[t] = local;
    sq[t] = lsum;
    __syncthreads();
    for (int o = 128; o; o >>= 1) {
        if (t < o) { sh[t] += sh[t + o]; sq[t] += sq[t + o]; }
        __syncthreads();
    }
    if (t == 0) {
        out[QN]     = (float)(1.25 * sq[0] / (double)QN);
        out[QN + 1] = (float)exp(-sh[0]);
    }
}

// ---------------------------------------------------------------------------
extern "C" void kernel_launch(void* const* d_in, const int* in_sizes, int n_in,
                              void* d_out, int out_size) {
    const float* in  = (const float*)d_in[0];
    const float* emb = (const float*)d_in[1];
    if (n_in >= 2 && in_sizes[0] == Dc * Kc) {  // defensive: inputs swapped?
        in  = (const float*)d_in[1];
        emb = (const float*)d_in[0];
    }
    float* out = (float*)d_out;

    cudaFuncSetAttribute(k_argmin_mma, cudaFuncAttributeMaxDynamicSharedMemorySize,
                         SMEM_TOTAL);

    k_prep_e<<<Kc / 32, 256>>>(emb);                       // #1 (zero fused)
    k_prep_x<<<dim3(HWc / 32, Dc / 32, Bc), dim3(32, 8)>>>(in);   // #2
    k_argmin_mma<<<Nrows / 128, 256, SMEM_TOTAL>>>();      // #3 (R14 exact)
    k_fallback<<<dim3(8, 256), 256>>>();                   // #4 -> profiled
    k_gather<<<dim3(HWc / 32, Bc), 256>>>(in, out);        // #5 (hist fused)
    k_final<<<1, 256>>>(out);                              // #6
}